// round 11
// baseline (speedup 1.0000x reference)
#include <cuda_runtime.h>
#include <cuda_fp16.h>
#include <math.h>
#include <stdint.h>

#define ND 1024
#define NF 4096
#define NE 8
#define NT 2048
#define NCAP 2048
#define TBM 128
#define TBN 128
#define TBK 32
#define NTHREADS 256

// -------- scratch (device globals; no allocations allowed) --------
__device__ int   g_count[NE];
__device__ int   g_tok[NE * NCAP];
__device__ float g_wgt[NE * NCAP];
__device__ __half g_xh[(size_t)NT * ND];
__device__ __half g_xl[(size_t)NT * ND];
__device__ __half g_w1h[(size_t)NE * ND * NF];  // [e][n(F)][k(D)]
__device__ __half g_w2h[(size_t)NE * NF * ND];  // [e][n(D)][k(F)]
__device__ __half g_hh[(size_t)NE * NCAP * NF];
__device__ __half g_hl[(size_t)NE * NCAP * NF];

// ==================== helpers ====================

__device__ __forceinline__ uint32_t smem_to_u32(const void* smem_ptr) {
    uint32_t addr;
    asm("{ .reg .u64 tmp; cvta.to.shared.u64 tmp, %1; cvt.u32.u64 %0, tmp; }"
        : "=r"(addr) : "l"(smem_ptr));
    return addr;
}

__device__ __forceinline__ void cp16(uint32_t smem_dst, const void* gsrc) {
    size_t gaddr = __cvta_generic_to_global(gsrc);
    asm volatile("cp.async.cg.shared.global [%0], [%1], 16;"
                 :: "r"(smem_dst), "l"(gaddr) : "memory");
}
#define CP_COMMIT() asm volatile("cp.async.commit_group;" ::: "memory")
template<int N>
__device__ __forceinline__ void cp_wait() {
    asm volatile("cp.async.wait_group %0;" :: "n"(N) : "memory");
}

__device__ __forceinline__ void ldsm4(uint32_t& r0, uint32_t& r1, uint32_t& r2,
                                      uint32_t& r3, uint32_t addr) {
    asm volatile("ldmatrix.sync.aligned.m8n8.x4.shared.b16 {%0,%1,%2,%3}, [%4];"
                 : "=r"(r0), "=r"(r1), "=r"(r2), "=r"(r3) : "r"(addr));
}

// warp mma: D(16x8,f32) += A(16x16,f16,row) * B(16x8,f16,col)
__device__ __forceinline__ void mma16816h(float* c, const uint32_t* a, const uint32_t* b) {
    asm volatile(
        "mma.sync.aligned.m16n8k16.row.col.f32.f16.f16.f32 "
        "{%0,%1,%2,%3}, {%4,%5,%6,%7}, {%8,%9}, {%0,%1,%2,%3};"
        : "+f"(c[0]), "+f"(c[1]), "+f"(c[2]), "+f"(c[3])
        : "r"(a[0]), "r"(a[1]), "r"(a[2]), "r"(a[3]), "r"(b[0]), "r"(b[1]));
}

__device__ __forceinline__ uint32_t pack_h2(__half a, __half b) {
    unsigned short sa = *reinterpret_cast<unsigned short*>(&a);
    unsigned short sb = *reinterpret_cast<unsigned short*>(&b);
    return (uint32_t)sa | ((uint32_t)sb << 16);
}

__device__ __forceinline__ void cvt8h(const float* f, uint4& hi) {
    unsigned short hs[8];
#pragma unroll
    for (int i = 0; i < 8; i++) {
        __half h = __float2half_rn(f[i]);
        hs[i] = *reinterpret_cast<unsigned short*>(&h);
    }
    hi.x = (uint32_t)hs[0] | ((uint32_t)hs[1] << 16);
    hi.y = (uint32_t)hs[2] | ((uint32_t)hs[3] << 16);
    hi.z = (uint32_t)hs[4] | ((uint32_t)hs[5] << 16);
    hi.w = (uint32_t)hs[6] | ((uint32_t)hs[7] << 16);
}

// ==================== precompute kernels ====================

__global__ void zero_kernel(float* __restrict__ out) {
    int i = blockIdx.x * blockDim.x + threadIdx.x;
    if (i < NT * ND) out[i] = 0.0f;
    if (i < NE) g_count[i] = 0;
}

__global__ void splitx_kernel(const float* __restrict__ x) {
    int i = blockIdx.x * blockDim.x + threadIdx.x;
    if (i < NT * ND / 2) {
        float2 v = ((const float2*)x)[i];
        __half h0 = __float2half_rn(v.x);
        __half h1 = __float2half_rn(v.y);
        __half l0 = __float2half_rn(v.x - __half2float(h0));
        __half l1 = __float2half_rn(v.y - __half2float(h1));
        ((uint32_t*)g_xh)[i] = pack_h2(h0, h1);
        ((uint32_t*)g_xl)[i] = pack_h2(l0, l1);
    }
}

// transpose W[e][k][n] fp32 -> Wh [e][n][k] fp16
__global__ void splitw_kernel(const float* __restrict__ Wsrc,
                              int kdim, int ndim, int which) {
    __shared__ float tile[64][65];
    int e = blockIdx.z;
    int n0 = blockIdx.x * 64;
    int k0 = blockIdx.y * 64;
    int tid = threadIdx.x;
    const float* src = Wsrc + (size_t)e * (size_t)kdim * (size_t)ndim;
#pragma unroll
    for (int i = 0; i < 16; i++) {
        int r = (tid >> 6) + i * 4;
        int c = tid & 63;
        tile[r][c] = src[(size_t)(k0 + r) * ndim + n0 + c];
    }
    __syncthreads();
    __half* Wh = which ? g_w1h : g_w2h;
    size_t base = (size_t)e * (size_t)kdim * (size_t)ndim;
    int nl = tid >> 2;
    int kq = (tid & 3) * 16;
#pragma unroll
    for (int half = 0; half < 2; half++) {
        float fv[8];
#pragma unroll
        for (int j = 0; j < 8; j++) fv[j] = tile[kq + half * 8 + j][nl];
        uint4 hi;
        cvt8h(fv, hi);
        size_t o = base + (size_t)(n0 + nl) * kdim + k0 + kq + half * 8;
        *(uint4*)(Wh + o) = hi;
    }
}

__global__ void router_kernel(const float* __restrict__ x,
                              const float* __restrict__ Wr,
                              const float* __restrict__ br) {
    int t = blockIdx.x;
    int lane = threadIdx.x;
    float acc[NE];
#pragma unroll
    for (int e = 0; e < NE; e++) acc[e] = 0.0f;
    const float* xr = x + (size_t)t * ND;
    for (int d = lane; d < ND; d += 32) {
        float xv = xr[d];
        const float* wr = Wr + (size_t)d * NE;
#pragma unroll
        for (int e = 0; e < NE; e++) acc[e] += xv * wr[e];
    }
#pragma unroll
    for (int e = 0; e < NE; e++) {
#pragma unroll
        for (int off = 16; off > 0; off >>= 1)
            acc[e] += __shfl_xor_sync(0xffffffffu, acc[e], off);
    }
    if (lane == 0) {
#pragma unroll
        for (int e = 0; e < NE; e++) acc[e] += br[e];
        int i0 = 0;
#pragma unroll
        for (int e = 1; e < NE; e++) if (acc[e] > acc[i0]) i0 = e;
        int i1 = (i0 == 0) ? 1 : 0;
#pragma unroll
        for (int e = 0; e < NE; e++) {
            if (e == i0) continue;
            if (acc[e] > acc[i1] || (acc[e] == acc[i1] && e < i1)) i1 = e;
        }
        float l0 = acc[i0], l1 = acc[i1];
        float e1 = expf(l1 - l0);
        float w0 = 1.0f / (1.0f + e1);
        float w1 = e1 * w0;
        int p0 = atomicAdd(&g_count[i0], 1);
        g_tok[i0 * NCAP + p0] = t;  g_wgt[i0 * NCAP + p0] = w0;
        int p1 = atomicAdd(&g_count[i1], 1);
        g_tok[i1 * NCAP + p1] = t;  g_wgt[i1 * NCAP + p1] = w1;
    }
}

// ==================== split-fp16 HMMA GEMM, cp.async + ldmatrix ====================
#define OFF_AH 0
#define OFF_AL 10240
#define OFF_BH 20480
#define STAGEB 30720
#define SMEM_REQ (2 * STAGEB + 512)

__global__ __launch_bounds__(NTHREADS, 2) void moe_mma_gemm(
    const float* __restrict__ bias,
    float* __restrict__ out,
    int kdim, int ldb, int is_ffn1)
{
    int e = blockIdx.z;
    int ne = g_count[e];
    int m0 = blockIdx.y * TBM;
    if (m0 >= ne) return;
    int n0 = blockIdx.x * TBN;
    int tid = threadIdx.x;
    int warp = tid >> 5;
    int lane = tid & 31;
    int wm = warp >> 2;
    int wn = warp & 3;
    int grp = lane >> 2;
    int tig = lane & 3;
    // ldmatrix lane addressing: row = lane&15, k-half = lane>>4
    int lrow = lane & 15;
    int lko = (lane >> 4) * 16;   // byte offset within 32B k16 chunk

    extern __shared__ char smbase[];
    uint32_t smu = smem_to_u32(smbase);
    int* rows = (int*)(smbase + 2 * STAGEB);

    if (is_ffn1 && tid < TBM) {
        int m = m0 + tid;
        rows[tid] = (m < ne) ? g_tok[e * NCAP + m] : -1;
    }
    __syncthreads();

    const __half* Whb = (is_ffn1 ? g_w1h : g_w2h) + (size_t)e * (size_t)kdim * (size_t)ldb;
    const __half* Ahb = is_ffn1 ? g_xh : (g_hh + (size_t)e * NCAP * NF);
    const __half* Alb = is_ffn1 ? g_xl : (g_hl + (size_t)e * NCAP * NF);
    size_t arow_stride = is_ffn1 ? ND : NF;

    auto fill = [&](int s, int kb) {
        int k0 = kb * TBK;
        uint32_t sb = smu + s * STAGEB;
        char* sp = smbase + s * STAGEB;
#pragma unroll
        for (int i = 0; i < 2; i++) {
            int u = tid + i * NTHREADS;
            int row = u >> 2;
            int part = u & 3;
            uint32_t off = row * 80 + part * 16;
            long arow;
            if (is_ffn1) arow = rows[row];
            else         arow = (m0 + row < ne) ? (m0 + row) : -1;
            if (arow >= 0) {
                const __half* sh = Ahb + (size_t)arow * arow_stride + k0 + part * 8;
                const __half* sl = Alb + (size_t)arow * arow_stride + k0 + part * 8;
                cp16(sb + OFF_AH + off, sh);
                cp16(sb + OFF_AL + off, sl);
            } else {
                *(uint4*)(sp + OFF_AH + off) = make_uint4(0, 0, 0, 0);
                *(uint4*)(sp + OFF_AL + off) = make_uint4(0, 0, 0, 0);
            }
            const __half* bh = Whb + (size_t)(n0 + row) * kdim + k0 + part * 8;
            cp16(sb + OFF_BH + off, bh);
        }
    };

    float acc[4][4][4];
#pragma unroll
    for (int i = 0; i < 4; i++)
#pragma unroll
        for (int j = 0; j < 4; j++)
#pragma unroll
            for (int q = 0; q < 4; q++) acc[i][j][q] = 0.0f;

    int nb = kdim / TBK;
    fill(0, 0);
    CP_COMMIT();

    for (int kb = 0; kb < nb; kb++) {
        if (kb + 1 < nb) {
            fill((kb + 1) & 1, kb + 1);
            CP_COMMIT();
            cp_wait<1>();
        } else {
            cp_wait<0>();
        }
        __syncthreads();

        uint32_t sb = smu + (kb & 1) * STAGEB;
#pragma unroll
        for (int s = 0; s < 2; s++) {
            uint32_t kbyte = s * 32 + lko;
            // B fragments: 2 x ldmatrix.x4 -> 4 n-tiles
            uint32_t bhf[4][2];
            {
                uint32_t baddr = sb + OFF_BH + (uint32_t)(wn * 32 + lrow) * 80 + kbyte;
                uint32_t r0, r1, r2, r3;
                ldsm4(r0, r1, r2, r3, baddr);
                bhf[0][0] = r0; bhf[0][1] = r2;
                bhf[1][0] = r1; bhf[1][1] = r3;
                ldsm4(r0, r1, r2, r3, baddr + 16 * 80);
                bhf[2][0] = r0; bhf[2][1] = r2;
                bhf[3][0] = r1; bhf[3][1] = r3;
            }
#pragma unroll
            for (int mt = 0; mt < 4; mt++) {
                uint32_t arow_addr = (uint32_t)(wm * 64 + mt * 16 + lrow) * 80 + kbyte;
                uint32_t ah[4], al[4];
                ldsm4(ah[0], ah[1], ah[2], ah[3], sb + OFF_AH + arow_addr);
                ldsm4(al[0], al[1], al[2], al[3], sb + OFF_AL + arow_addr);
#pragma unroll
                for (int nt = 0; nt < 4; nt++) {
                    mma16816h(acc[mt][nt], ah, bhf[nt]);
                    mma16816h(acc[mt][nt], al, bhf[nt]);
                }
            }
        }
        __syncthreads();
    }

    // ---- epilogue ----
#pragma unroll
    for (int mt = 0; mt < 4; mt++) {
#pragma unroll
        for (int half = 0; half < 2; half++) {
            int m = m0 + wm * 64 + mt * 16 + grp + half * 8;
            if (m >= ne) continue;
            if (is_ffn1) {
                const float* bb = bias + (size_t)e * NF;
                __half* hh = g_hh + (size_t)e * NCAP * NF + (size_t)m * NF;
                __half* hl = g_hl + (size_t)e * NCAP * NF + (size_t)m * NF;
#pragma unroll
                for (int nt = 0; nt < 4; nt++) {
                    int n = n0 + wn * 32 + nt * 8 + tig * 2;
                    float v0 = acc[mt][nt][half * 2 + 0] + bb[n];
                    float v1 = acc[mt][nt][half * 2 + 1] + bb[n + 1];
                    v0 = 0.5f * v0 * (1.0f + erff(v0 * 0.70710678118654752f));
                    v1 = 0.5f * v1 * (1.0f + erff(v1 * 0.70710678118654752f));
                    __half h0 = __float2half_rn(v0);
                    __half h1 = __float2half_rn(v1);
                    __half l0 = __float2half_rn(v0 - __half2float(h0));
                    __half l1 = __float2half_rn(v1 - __half2float(h1));
                    *(uint32_t*)(hh + n) = pack_h2(h0, h1);
                    *(uint32_t*)(hl + n) = pack_h2(l0, l1);
                }
            } else {
                int tok = g_tok[e * NCAP + m];
                float wgt = g_wgt[e * NCAP + m];
                float* orow = out + (size_t)tok * ND;
                const float* bb = bias + (size_t)e * ND;
#pragma unroll
                for (int nt = 0; nt < 4; nt++) {
                    int n = n0 + wn * 32 + nt * 8 + tig * 2;
                    float v0 = wgt * (acc[mt][nt][half * 2 + 0] + bb[n]);
                    float v1 = wgt * (acc[mt][nt][half * 2 + 1] + bb[n + 1]);
                    atomicAdd(&orow[n], v0);
                    atomicAdd(&orow[n + 1], v1);
                }
            }
        }
    }
}

// ==================== host launcher ====================

extern "C" void kernel_launch(void* const* d_in, const int* in_sizes, int n_in,
                              void* d_out, int out_size) {
    const float* x  = (const float*)d_in[0];
    const float* Wr = (const float*)d_in[1];
    const float* br = (const float*)d_in[2];
    const float* W1 = (const float*)d_in[3];
    const float* b1 = (const float*)d_in[4];
    const float* W2 = (const float*)d_in[5];
    const float* b2 = (const float*)d_in[6];
    float* out = (float*)d_out;

    cudaFuncSetAttribute(moe_mma_gemm,
                         cudaFuncAttributeMaxDynamicSharedMemorySize, SMEM_REQ);

    zero_kernel<<<(NT * ND + 255) / 256, 256>>>(out);
    splitx_kernel<<<(NT * ND / 2 + 255) / 256, 256>>>(x);
    splitw_kernel<<<dim3(NF / 64, ND / 64, NE), 256>>>(W1, ND, NF, 1);
    splitw_kernel<<<dim3(ND / 64, NF / 64, NE), 256>>>(W2, NF, ND, 0);
    router_kernel<<<NT, 32>>>(x, Wr, br);
    moe_mma_gemm<<<dim3(NF / TBN, NCAP / TBM, NE), NTHREADS, SMEM_REQ>>>(
        b1, out, ND, NF, 1);
    moe_mma_gemm<<<dim3(ND / TBN, NCAP / TBM, NE), NTHREADS, SMEM_REQ>>>(
        b2, out, NF, ND, 0);
}

// round 12
// speedup vs baseline: 1.0829x; 1.0829x over previous
#include <cuda_runtime.h>
#include <cuda_fp16.h>
#include <math.h>
#include <stdint.h>

#define ND 1024
#define NF 4096
#define NE 8
#define NT 2048
#define NCAP 2048
#define TBM 128
#define TBN 128
#define TBK 32
#define NTHREADS 256

// -------- scratch (device globals; no allocations allowed) --------
__device__ int   g_count[NE];
__device__ int   g_tok[NE * NCAP];
__device__ float g_wgt[NE * NCAP];
__device__ __half g_xh[(size_t)NT * ND];
__device__ __half g_xl[(size_t)NT * ND];
__device__ __half g_w1h[(size_t)NE * ND * NF];  // [e][n(F)][k(D)]
__device__ __half g_w2h[(size_t)NE * NF * ND];  // [e][n(D)][k(F)]
__device__ __half g_hh[(size_t)NE * NCAP * NF];
__device__ __half g_hl[(size_t)NE * NCAP * NF];

// ==================== helpers ====================

__device__ __forceinline__ uint32_t smem_to_u32(const void* smem_ptr) {
    uint32_t addr;
    asm("{ .reg .u64 tmp; cvta.to.shared.u64 tmp, %1; cvt.u32.u64 %0, tmp; }"
        : "=r"(addr) : "l"(smem_ptr));
    return addr;
}

__device__ __forceinline__ void cp16(uint32_t smem_dst, const void* gsrc) {
    size_t gaddr = __cvta_generic_to_global(gsrc);
    asm volatile("cp.async.cg.shared.global [%0], [%1], 16;"
                 :: "r"(smem_dst), "l"(gaddr) : "memory");
}
#define CP_COMMIT() asm volatile("cp.async.commit_group;" ::: "memory")
template<int N>
__device__ __forceinline__ void cp_wait() {
    asm volatile("cp.async.wait_group %0;" :: "n"(N) : "memory");
}

// warp mma: D(16x8,f32) += A(16x16,f16,row) * B(16x8,f16,col)
__device__ __forceinline__ void mma16816h(float* c, const uint32_t* a, const uint32_t* b) {
    asm volatile(
        "mma.sync.aligned.m16n8k16.row.col.f32.f16.f16.f32 "
        "{%0,%1,%2,%3}, {%4,%5,%6,%7}, {%8,%9}, {%0,%1,%2,%3};"
        : "+f"(c[0]), "+f"(c[1]), "+f"(c[2]), "+f"(c[3])
        : "r"(a[0]), "r"(a[1]), "r"(a[2]), "r"(a[3]), "r"(b[0]), "r"(b[1]));
}

__device__ __forceinline__ uint32_t pack_h2(__half a, __half b) {
    unsigned short sa = *reinterpret_cast<unsigned short*>(&a);
    unsigned short sb = *reinterpret_cast<unsigned short*>(&b);
    return (uint32_t)sa | ((uint32_t)sb << 16);
}

__device__ __forceinline__ void cvt8h(const float* f, uint4& hi) {
    unsigned short hs[8];
#pragma unroll
    for (int i = 0; i < 8; i++) {
        __half h = __float2half_rn(f[i]);
        hs[i] = *reinterpret_cast<unsigned short*>(&h);
    }
    hi.x = (uint32_t)hs[0] | ((uint32_t)hs[1] << 16);
    hi.y = (uint32_t)hs[2] | ((uint32_t)hs[3] << 16);
    hi.z = (uint32_t)hs[4] | ((uint32_t)hs[5] << 16);
    hi.w = (uint32_t)hs[6] | ((uint32_t)hs[7] << 16);
}

// ==================== precompute kernels ====================

__global__ void zero_kernel(float* __restrict__ out) {
    int i = blockIdx.x * blockDim.x + threadIdx.x;
    if (i < NT * ND) out[i] = 0.0f;
    if (i < NE) g_count[i] = 0;
}

__global__ void splitx_kernel(const float* __restrict__ x) {
    int i = blockIdx.x * blockDim.x + threadIdx.x;
    if (i < NT * ND / 2) {
        float2 v = ((const float2*)x)[i];
        __half h0 = __float2half_rn(v.x);
        __half h1 = __float2half_rn(v.y);
        __half l0 = __float2half_rn(v.x - __half2float(h0));
        __half l1 = __float2half_rn(v.y - __half2float(h1));
        ((uint32_t*)g_xh)[i] = pack_h2(h0, h1);
        ((uint32_t*)g_xl)[i] = pack_h2(l0, l1);
    }
}

// transpose W[e][k][n] fp32 -> Wh [e][n][k] fp16
__global__ void splitw_kernel(const float* __restrict__ Wsrc,
                              int kdim, int ndim, int which) {
    __shared__ float tile[64][65];
    int e = blockIdx.z;
    int n0 = blockIdx.x * 64;
    int k0 = blockIdx.y * 64;
    int tid = threadIdx.x;
    const float* src = Wsrc + (size_t)e * (size_t)kdim * (size_t)ndim;
#pragma unroll
    for (int i = 0; i < 16; i++) {
        int r = (tid >> 6) + i * 4;
        int c = tid & 63;
        tile[r][c] = src[(size_t)(k0 + r) * ndim + n0 + c];
    }
    __syncthreads();
    __half* Wh = which ? g_w1h : g_w2h;
    size_t base = (size_t)e * (size_t)kdim * (size_t)ndim;
    int nl = tid >> 2;
    int kq = (tid & 3) * 16;
#pragma unroll
    for (int half = 0; half < 2; half++) {
        float fv[8];
#pragma unroll
        for (int j = 0; j < 8; j++) fv[j] = tile[kq + half * 8 + j][nl];
        uint4 hi;
        cvt8h(fv, hi);
        size_t o = base + (size_t)(n0 + nl) * kdim + k0 + kq + half * 8;
        *(uint4*)(Wh + o) = hi;
    }
}

__global__ void router_kernel(const float* __restrict__ x,
                              const float* __restrict__ Wr,
                              const float* __restrict__ br) {
    int t = blockIdx.x;
    int lane = threadIdx.x;
    float acc[NE];
#pragma unroll
    for (int e = 0; e < NE; e++) acc[e] = 0.0f;
    const float* xr = x + (size_t)t * ND;
    for (int d = lane; d < ND; d += 32) {
        float xv = xr[d];
        const float* wr = Wr + (size_t)d * NE;
#pragma unroll
        for (int e = 0; e < NE; e++) acc[e] += xv * wr[e];
    }
#pragma unroll
    for (int e = 0; e < NE; e++) {
#pragma unroll
        for (int off = 16; off > 0; off >>= 1)
            acc[e] += __shfl_xor_sync(0xffffffffu, acc[e], off);
    }
    if (lane == 0) {
#pragma unroll
        for (int e = 0; e < NE; e++) acc[e] += br[e];
        int i0 = 0;
#pragma unroll
        for (int e = 1; e < NE; e++) if (acc[e] > acc[i0]) i0 = e;
        int i1 = (i0 == 0) ? 1 : 0;
#pragma unroll
        for (int e = 0; e < NE; e++) {
            if (e == i0) continue;
            if (acc[e] > acc[i1] || (acc[e] == acc[i1] && e < i1)) i1 = e;
        }
        float l0 = acc[i0], l1 = acc[i1];
        float e1 = expf(l1 - l0);
        float w0 = 1.0f / (1.0f + e1);
        float w1 = e1 * w0;
        int p0 = atomicAdd(&g_count[i0], 1);
        g_tok[i0 * NCAP + p0] = t;  g_wgt[i0 * NCAP + p0] = w0;
        int p1 = atomicAdd(&g_count[i1], 1);
        g_tok[i1 * NCAP + p1] = t;  g_wgt[i1 * NCAP + p1] = w1;
    }
}

// ==================== split-fp16 HMMA GEMM, cp.async double-buffered ====================
#define OFF_AH 0
#define OFF_AL 10240
#define OFF_BH 20480
#define STAGEB 30720
#define SMEM_REQ (2 * STAGEB + 512)

__global__ __launch_bounds__(NTHREADS, 2) void moe_mma_gemm(
    const float* __restrict__ bias,
    float* __restrict__ out,
    int kdim, int ldb, int is_ffn1)
{
    int e = blockIdx.z;
    int ne = g_count[e];
    int m0 = blockIdx.y * TBM;
    if (m0 >= ne) return;
    int n0 = blockIdx.x * TBN;
    int tid = threadIdx.x;
    int warp = tid >> 5;
    int lane = tid & 31;
    int wm = warp >> 2;
    int wn = warp & 3;
    int grp = lane >> 2;
    int tig = lane & 3;

    extern __shared__ char smbase[];
    uint32_t smu = smem_to_u32(smbase);
    int* rows = (int*)(smbase + 2 * STAGEB);

    if (is_ffn1 && tid < TBM) {
        int m = m0 + tid;
        rows[tid] = (m < ne) ? g_tok[e * NCAP + m] : -1;
    }
    __syncthreads();

    const __half* Whb = (is_ffn1 ? g_w1h : g_w2h) + (size_t)e * (size_t)kdim * (size_t)ldb;
    const __half* Ahb = is_ffn1 ? g_xh : (g_hh + (size_t)e * NCAP * NF);
    const __half* Alb = is_ffn1 ? g_xl : (g_hl + (size_t)e * NCAP * NF);
    size_t arow_stride = is_ffn1 ? ND : NF;

    auto fill = [&](int s, int kb) {
        int k0 = kb * TBK;
        uint32_t sb = smu + s * STAGEB;
        char* sp = smbase + s * STAGEB;
#pragma unroll
        for (int i = 0; i < 2; i++) {
            int u = tid + i * NTHREADS;
            int row = u >> 2;
            int part = u & 3;
            uint32_t off = row * 80 + part * 16;
            long arow;
            if (is_ffn1) arow = rows[row];
            else         arow = (m0 + row < ne) ? (m0 + row) : -1;
            if (arow >= 0) {
                const __half* sh = Ahb + (size_t)arow * arow_stride + k0 + part * 8;
                const __half* sl = Alb + (size_t)arow * arow_stride + k0 + part * 8;
                cp16(sb + OFF_AH + off, sh);
                cp16(sb + OFF_AL + off, sl);
            } else {
                *(uint4*)(sp + OFF_AH + off) = make_uint4(0, 0, 0, 0);
                *(uint4*)(sp + OFF_AL + off) = make_uint4(0, 0, 0, 0);
            }
            const __half* bh = Whb + (size_t)(n0 + row) * kdim + k0 + part * 8;
            cp16(sb + OFF_BH + off, bh);
        }
    };

    float acc[4][4][4];
#pragma unroll
    for (int i = 0; i < 4; i++)
#pragma unroll
        for (int j = 0; j < 4; j++)
#pragma unroll
            for (int q = 0; q < 4; q++) acc[i][j][q] = 0.0f;

    int nb = kdim / TBK;
    fill(0, 0);
    CP_COMMIT();

    for (int kb = 0; kb < nb; kb++) {
        if (kb + 1 < nb) {
            fill((kb + 1) & 1, kb + 1);
            CP_COMMIT();
            cp_wait<1>();
        } else {
            cp_wait<0>();
        }
        __syncthreads();

        char* sp = smbase + (kb & 1) * STAGEB;
#pragma unroll
        for (int s = 0; s < 2; s++) {
            int kc = s * 16 + tig * 2;
            uint32_t bhf[4][2];
#pragma unroll
            for (int nt = 0; nt < 4; nt++) {
                int n = wn * 32 + nt * 8 + grp;
                const char* bp = sp + n * 80 + kc * 2;
                bhf[nt][0] = *(const uint32_t*)(bp + OFF_BH);
                bhf[nt][1] = *(const uint32_t*)(bp + OFF_BH + 16);
            }
#pragma unroll
            for (int mt = 0; mt < 4; mt++) {
                int m = wm * 64 + mt * 16 + grp;
                const char* ap0 = sp + m * 80 + kc * 2;
                const char* ap1 = sp + (m + 8) * 80 + kc * 2;
                uint32_t ah[4], al[4];
                ah[0] = *(const uint32_t*)(ap0 + OFF_AH);
                ah[1] = *(const uint32_t*)(ap1 + OFF_AH);
                ah[2] = *(const uint32_t*)(ap0 + OFF_AH + 16);
                ah[3] = *(const uint32_t*)(ap1 + OFF_AH + 16);
                al[0] = *(const uint32_t*)(ap0 + OFF_AL);
                al[1] = *(const uint32_t*)(ap1 + OFF_AL);
                al[2] = *(const uint32_t*)(ap0 + OFF_AL + 16);
                al[3] = *(const uint32_t*)(ap1 + OFF_AL + 16);
                // all hi MMAs first, then all lo: RAW reuse distance 4
#pragma unroll
                for (int nt = 0; nt < 4; nt++)
                    mma16816h(acc[mt][nt], ah, bhf[nt]);
#pragma unroll
                for (int nt = 0; nt < 4; nt++)
                    mma16816h(acc[mt][nt], al, bhf[nt]);
            }
        }
        __syncthreads();
    }

    // ---- epilogue ----
#pragma unroll
    for (int mt = 0; mt < 4; mt++) {
#pragma unroll
        for (int half = 0; half < 2; half++) {
            int m = m0 + wm * 64 + mt * 16 + grp + half * 8;
            if (m >= ne) continue;
            if (is_ffn1) {
                const float* bb = bias + (size_t)e * NF;
                __half* hh = g_hh + (size_t)e * NCAP * NF + (size_t)m * NF;
                __half* hl = g_hl + (size_t)e * NCAP * NF + (size_t)m * NF;
#pragma unroll
                for (int nt = 0; nt < 4; nt++) {
                    int n = n0 + wn * 32 + nt * 8 + tig * 2;
                    float v0 = acc[mt][nt][half * 2 + 0] + bb[n];
                    float v1 = acc[mt][nt][half * 2 + 1] + bb[n + 1];
                    v0 = 0.5f * v0 * (1.0f + erff(v0 * 0.70710678118654752f));
                    v1 = 0.5f * v1 * (1.0f + erff(v1 * 0.70710678118654752f));
                    __half h0 = __float2half_rn(v0);
                    __half h1 = __float2half_rn(v1);
                    __half l0 = __float2half_rn(v0 - __half2float(h0));
                    __half l1 = __float2half_rn(v1 - __half2float(h1));
                    *(uint32_t*)(hh + n) = pack_h2(h0, h1);
                    *(uint32_t*)(hl + n) = pack_h2(l0, l1);
                }
            } else {
                int tok = g_tok[e * NCAP + m];
                float wgt = g_wgt[e * NCAP + m];
                float* orow = out + (size_t)tok * ND;
                const float* bb = bias + (size_t)e * ND;
#pragma unroll
                for (int nt = 0; nt < 4; nt++) {
                    int n = n0 + wn * 32 + nt * 8 + tig * 2;
                    float v0 = wgt * (acc[mt][nt][half * 2 + 0] + bb[n]);
                    float v1 = wgt * (acc[mt][nt][half * 2 + 1] + bb[n + 1]);
                    atomicAdd(&orow[n], v0);
                    atomicAdd(&orow[n + 1], v1);
                }
            }
        }
    }
}

// ==================== host launcher ====================

extern "C" void kernel_launch(void* const* d_in, const int* in_sizes, int n_in,
                              void* d_out, int out_size) {
    const float* x  = (const float*)d_in[0];
    const float* Wr = (const float*)d_in[1];
    const float* br = (const float*)d_in[2];
    const float* W1 = (const float*)d_in[3];
    const float* b1 = (const float*)d_in[4];
    const float* W2 = (const float*)d_in[5];
    const float* b2 = (const float*)d_in[6];
    float* out = (float*)d_out;

    cudaFuncSetAttribute(moe_mma_gemm,
                         cudaFuncAttributeMaxDynamicSharedMemorySize, SMEM_REQ);

    zero_kernel<<<(NT * ND + 255) / 256, 256>>>(out);
    splitx_kernel<<<(NT * ND / 2 + 255) / 256, 256>>>(x);
    splitw_kernel<<<dim3(NF / 64, ND / 64, NE), 256>>>(W1, ND, NF, 1);
    splitw_kernel<<<dim3(ND / 64, NF / 64, NE), 256>>>(W2, NF, ND, 0);
    router_kernel<<<NT, 32>>>(x, Wr, br);
    moe_mma_gemm<<<dim3(NF / TBN, NCAP / TBM, NE), NTHREADS, SMEM_REQ>>>(
        b1, out, ND, NF, 1);
    moe_mma_gemm<<<dim3(ND / TBN, NCAP / TBM, NE), NTHREADS, SMEM_REQ>>>(
        b2, out, NF, ND, 0);
}

// round 13
// speedup vs baseline: 1.5602x; 1.4408x over previous
#include <cuda_runtime.h>
#include <cuda_fp16.h>
#include <math.h>
#include <stdint.h>

#define ND 1024
#define NF 4096
#define NE 8
#define NT 2048
#define NCAP 2048
#define TBM 128
#define TBN 128
#define TBK 32
#define NTHREADS 256

// -------- scratch (device globals; no allocations allowed) --------
__device__ int   g_count[NE];
__device__ int   g_tok[NE * NCAP];
__device__ float g_wgt[NE * NCAP];
__device__ __half g_xh[(size_t)NT * ND];
__device__ __half g_w1h[(size_t)NE * ND * NF];  // [e][n(F)][k(D)]
__device__ __half g_w2h[(size_t)NE * NF * ND];  // [e][n(D)][k(F)]
__device__ __half g_hh[(size_t)NE * NCAP * NF];

// ==================== helpers ====================

__device__ __forceinline__ uint32_t smem_to_u32(const void* smem_ptr) {
    uint32_t addr;
    asm("{ .reg .u64 tmp; cvta.to.shared.u64 tmp, %1; cvt.u32.u64 %0, tmp; }"
        : "=r"(addr) : "l"(smem_ptr));
    return addr;
}

__device__ __forceinline__ void cp16(uint32_t smem_dst, const void* gsrc) {
    size_t gaddr = __cvta_generic_to_global(gsrc);
    asm volatile("cp.async.cg.shared.global [%0], [%1], 16;"
                 :: "r"(smem_dst), "l"(gaddr) : "memory");
}
#define CP_COMMIT() asm volatile("cp.async.commit_group;" ::: "memory")
template<int N>
__device__ __forceinline__ void cp_wait() {
    asm volatile("cp.async.wait_group %0;" :: "n"(N) : "memory");
}

// warp mma: D(16x8,f32) += A(16x16,f16,row) * B(16x8,f16,col)
__device__ __forceinline__ void mma16816h(float* c, const uint32_t* a, const uint32_t* b) {
    asm volatile(
        "mma.sync.aligned.m16n8k16.row.col.f32.f16.f16.f32 "
        "{%0,%1,%2,%3}, {%4,%5,%6,%7}, {%8,%9}, {%0,%1,%2,%3};"
        : "+f"(c[0]), "+f"(c[1]), "+f"(c[2]), "+f"(c[3])
        : "r"(a[0]), "r"(a[1]), "r"(a[2]), "r"(a[3]), "r"(b[0]), "r"(b[1]));
}

__device__ __forceinline__ uint32_t pack_h2(__half a, __half b) {
    unsigned short sa = *reinterpret_cast<unsigned short*>(&a);
    unsigned short sb = *reinterpret_cast<unsigned short*>(&b);
    return (uint32_t)sa | ((uint32_t)sb << 16);
}

__device__ __forceinline__ void cvt8h(const float* f, uint4& hi) {
    unsigned short hs[8];
#pragma unroll
    for (int i = 0; i < 8; i++) {
        __half h = __float2half_rn(f[i]);
        hs[i] = *reinterpret_cast<unsigned short*>(&h);
    }
    hi.x = (uint32_t)hs[0] | ((uint32_t)hs[1] << 16);
    hi.y = (uint32_t)hs[2] | ((uint32_t)hs[3] << 16);
    hi.z = (uint32_t)hs[4] | ((uint32_t)hs[5] << 16);
    hi.w = (uint32_t)hs[6] | ((uint32_t)hs[7] << 16);
}

// ==================== precompute kernels ====================

__global__ void zero_kernel(float* __restrict__ out) {
    int i = blockIdx.x * blockDim.x + threadIdx.x;
    if (i < NT * ND) out[i] = 0.0f;
    if (i < NE) g_count[i] = 0;
}

__global__ void splitx_kernel(const float* __restrict__ x) {
    int i = blockIdx.x * blockDim.x + threadIdx.x;
    if (i < NT * ND / 2) {
        float2 v = ((const float2*)x)[i];
        ((uint32_t*)g_xh)[i] = pack_h2(__float2half_rn(v.x), __float2half_rn(v.y));
    }
}

// transpose W[e][k][n] fp32 -> Wh [e][n][k] fp16
__global__ void splitw_kernel(const float* __restrict__ Wsrc,
                              int kdim, int ndim, int which) {
    __shared__ float tile[64][65];
    int e = blockIdx.z;
    int n0 = blockIdx.x * 64;
    int k0 = blockIdx.y * 64;
    int tid = threadIdx.x;
    const float* src = Wsrc + (size_t)e * (size_t)kdim * (size_t)ndim;
#pragma unroll
    for (int i = 0; i < 16; i++) {
        int r = (tid >> 6) + i * 4;
        int c = tid & 63;
        tile[r][c] = src[(size_t)(k0 + r) * ndim + n0 + c];
    }
    __syncthreads();
    __half* Wh = which ? g_w1h : g_w2h;
    size_t base = (size_t)e * (size_t)kdim * (size_t)ndim;
    int nl = tid >> 2;
    int kq = (tid & 3) * 16;
#pragma unroll
    for (int half = 0; half < 2; half++) {
        float fv[8];
#pragma unroll
        for (int j = 0; j < 8; j++) fv[j] = tile[kq + half * 8 + j][nl];
        uint4 hi;
        cvt8h(fv, hi);
        size_t o = base + (size_t)(n0 + nl) * kdim + k0 + kq + half * 8;
        *(uint4*)(Wh + o) = hi;
    }
}

__global__ void router_kernel(const float* __restrict__ x,
                              const float* __restrict__ Wr,
                              const float* __restrict__ br) {
    int t = blockIdx.x;
    int lane = threadIdx.x;
    float acc[NE];
#pragma unroll
    for (int e = 0; e < NE; e++) acc[e] = 0.0f;
    const float* xr = x + (size_t)t * ND;
    for (int d = lane; d < ND; d += 32) {
        float xv = xr[d];
        const float* wr = Wr + (size_t)d * NE;
#pragma unroll
        for (int e = 0; e < NE; e++) acc[e] += xv * wr[e];
    }
#pragma unroll
    for (int e = 0; e < NE; e++) {
#pragma unroll
        for (int off = 16; off > 0; off >>= 1)
            acc[e] += __shfl_xor_sync(0xffffffffu, acc[e], off);
    }
    if (lane == 0) {
#pragma unroll
        for (int e = 0; e < NE; e++) acc[e] += br[e];
        int i0 = 0;
#pragma unroll
        for (int e = 1; e < NE; e++) if (acc[e] > acc[i0]) i0 = e;
        int i1 = (i0 == 0) ? 1 : 0;
#pragma unroll
        for (int e = 0; e < NE; e++) {
            if (e == i0) continue;
            if (acc[e] > acc[i1] || (acc[e] == acc[i1] && e < i1)) i1 = e;
        }
        float l0 = acc[i0], l1 = acc[i1];
        float e1 = expf(l1 - l0);
        float w0 = 1.0f / (1.0f + e1);
        float w1 = e1 * w0;
        int p0 = atomicAdd(&g_count[i0], 1);
        g_tok[i0 * NCAP + p0] = t;  g_wgt[i0 * NCAP + p0] = w0;
        int p1 = atomicAdd(&g_count[i1], 1);
        g_tok[i1 * NCAP + p1] = t;  g_wgt[i1 * NCAP + p1] = w1;
    }
}

// ==================== fp16 HMMA GEMM, cp.async double-buffered ====================
#define OFF_BH 10240
#define STAGEB 20480
#define SMEM_REQ (2 * STAGEB + 512)

__global__ __launch_bounds__(NTHREADS, 2) void moe_mma_gemm(
    const float* __restrict__ bias,
    float* __restrict__ out,
    int kdim, int ldb, int is_ffn1)
{
    int e = blockIdx.z;
    int ne = g_count[e];
    int m0 = blockIdx.y * TBM;
    if (m0 >= ne) return;
    int n0 = blockIdx.x * TBN;
    int tid = threadIdx.x;
    int warp = tid >> 5;
    int lane = tid & 31;
    int wm = warp >> 2;
    int wn = warp & 3;
    int grp = lane >> 2;
    int tig = lane & 3;

    extern __shared__ char smbase[];
    uint32_t smu = smem_to_u32(smbase);
    int* rows = (int*)(smbase + 2 * STAGEB);

    if (is_ffn1 && tid < TBM) {
        int m = m0 + tid;
        rows[tid] = (m < ne) ? g_tok[e * NCAP + m] : -1;
    }
    __syncthreads();

    const __half* Whb = (is_ffn1 ? g_w1h : g_w2h) + (size_t)e * (size_t)kdim * (size_t)ldb;
    const __half* Ahb = is_ffn1 ? g_xh : (g_hh + (size_t)e * NCAP * NF);
    size_t arow_stride = is_ffn1 ? ND : NF;

    auto fill = [&](int s, int kb) {
        int k0 = kb * TBK;
        uint32_t sb = smu + s * STAGEB;
        char* sp = smbase + s * STAGEB;
#pragma unroll
        for (int i = 0; i < 2; i++) {
            int u = tid + i * NTHREADS;
            int row = u >> 2;
            int part = u & 3;
            uint32_t off = row * 80 + part * 16;
            long arow;
            if (is_ffn1) arow = rows[row];
            else         arow = (m0 + row < ne) ? (m0 + row) : -1;
            if (arow >= 0) {
                const __half* sh = Ahb + (size_t)arow * arow_stride + k0 + part * 8;
                cp16(sb + off, sh);
            } else {
                *(uint4*)(sp + off) = make_uint4(0, 0, 0, 0);
            }
            const __half* bh = Whb + (size_t)(n0 + row) * kdim + k0 + part * 8;
            cp16(sb + OFF_BH + off, bh);
        }
    };

    float acc[4][4][4];
#pragma unroll
    for (int i = 0; i < 4; i++)
#pragma unroll
        for (int j = 0; j < 4; j++)
#pragma unroll
            for (int q = 0; q < 4; q++) acc[i][j][q] = 0.0f;

    int nb = kdim / TBK;
    fill(0, 0);
    CP_COMMIT();

    for (int kb = 0; kb < nb; kb++) {
        if (kb + 1 < nb) {
            fill((kb + 1) & 1, kb + 1);
            CP_COMMIT();
            cp_wait<1>();
        } else {
            cp_wait<0>();
        }
        __syncthreads();

        char* sp = smbase + (kb & 1) * STAGEB;
#pragma unroll
        for (int s = 0; s < 2; s++) {
            int kc = s * 16 + tig * 2;
            uint32_t bhf[4][2];
#pragma unroll
            for (int nt = 0; nt < 4; nt++) {
                int n = wn * 32 + nt * 8 + grp;
                const char* bp = sp + OFF_BH + n * 80 + kc * 2;
                bhf[nt][0] = *(const uint32_t*)(bp);
                bhf[nt][1] = *(const uint32_t*)(bp + 16);
            }
#pragma unroll
            for (int mt = 0; mt < 4; mt++) {
                int m = wm * 64 + mt * 16 + grp;
                const char* ap0 = sp + m * 80 + kc * 2;
                const char* ap1 = sp + (m + 8) * 80 + kc * 2;
                uint32_t ah[4];
                ah[0] = *(const uint32_t*)(ap0);
                ah[1] = *(const uint32_t*)(ap1);
                ah[2] = *(const uint32_t*)(ap0 + 16);
                ah[3] = *(const uint32_t*)(ap1 + 16);
#pragma unroll
                for (int nt = 0; nt < 4; nt++)
                    mma16816h(acc[mt][nt], ah, bhf[nt]);
            }
        }
        __syncthreads();
    }

    // ---- epilogue ----
#pragma unroll
    for (int mt = 0; mt < 4; mt++) {
#pragma unroll
        for (int half = 0; half < 2; half++) {
            int m = m0 + wm * 64 + mt * 16 + grp + half * 8;
            if (m >= ne) continue;
            if (is_ffn1) {
                const float* bb = bias + (size_t)e * NF;
                __half* hh = g_hh + (size_t)e * NCAP * NF + (size_t)m * NF;
#pragma unroll
                for (int nt = 0; nt < 4; nt++) {
                    int n = n0 + wn * 32 + nt * 8 + tig * 2;
                    float v0 = acc[mt][nt][half * 2 + 0] + bb[n];
                    float v1 = acc[mt][nt][half * 2 + 1] + bb[n + 1];
                    v0 = 0.5f * v0 * (1.0f + erff(v0 * 0.70710678118654752f));
                    v1 = 0.5f * v1 * (1.0f + erff(v1 * 0.70710678118654752f));
                    *(uint32_t*)(hh + n) = pack_h2(__float2half_rn(v0), __float2half_rn(v1));
                }
            } else {
                int tok = g_tok[e * NCAP + m];
                float wgt = g_wgt[e * NCAP + m];
                float* orow = out + (size_t)tok * ND;
                const float* bb = bias + (size_t)e * ND;
#pragma unroll
                for (int nt = 0; nt < 4; nt++) {
                    int n = n0 + wn * 32 + nt * 8 + tig * 2;
                    float v0 = wgt * (acc[mt][nt][half * 2 + 0] + bb[n]);
                    float v1 = wgt * (acc[mt][nt][half * 2 + 1] + bb[n + 1]);
                    atomicAdd(&orow[n], v0);
                    atomicAdd(&orow[n + 1], v1);
                }
            }
        }
    }
}

// ==================== host launcher ====================

extern "C" void kernel_launch(void* const* d_in, const int* in_sizes, int n_in,
                              void* d_out, int out_size) {
    const float* x  = (const float*)d_in[0];
    const float* Wr = (const float*)d_in[1];
    const float* br = (const float*)d_in[2];
    const float* W1 = (const float*)d_in[3];
    const float* b1 = (const float*)d_in[4];
    const float* W2 = (const float*)d_in[5];
    const float* b2 = (const float*)d_in[6];
    float* out = (float*)d_out;

    cudaFuncSetAttribute(moe_mma_gemm,
                         cudaFuncAttributeMaxDynamicSharedMemorySize, SMEM_REQ);

    zero_kernel<<<(NT * ND + 255) / 256, 256>>>(out);
    splitx_kernel<<<(NT * ND / 2 + 255) / 256, 256>>>(x);
    splitw_kernel<<<dim3(NF / 64, ND / 64, NE), 256>>>(W1, ND, NF, 1);
    splitw_kernel<<<dim3(ND / 64, NF / 64, NE), 256>>>(W2, NF, ND, 0);
    router_kernel<<<NT, 32>>>(x, Wr, br);
    moe_mma_gemm<<<dim3(NF / TBN, NCAP / TBM, NE), NTHREADS, SMEM_REQ>>>(
        b1, out, ND, NF, 1);
    moe_mma_gemm<<<dim3(ND / TBN, NCAP / TBM, NE), NTHREADS, SMEM_REQ>>>(
        b2, out, NF, ND, 0);
}

// round 14
// speedup vs baseline: 1.6379x; 1.0498x over previous
#include <cuda_runtime.h>
#include <cuda_fp16.h>
#include <math.h>
#include <stdint.h>

#define ND 1024
#define NF 4096
#define NE 8
#define NT 2048
#define NCAP 2048
#define TBM 128
#define TBN 128
#define TBK 64
#define NTHREADS 256
#define ROWB 144   // smem row stride bytes (128 data + 16 pad)

// -------- scratch (device globals; no allocations allowed) --------
__device__ int   g_count[NE];
__device__ int   g_tok[NE * NCAP];
__device__ float g_wgt[NE * NCAP];
__device__ __half g_xh[(size_t)NT * ND];
__device__ __half g_w1h[(size_t)NE * ND * NF];  // [e][n(F)][k(D)]
__device__ __half g_w2h[(size_t)NE * NF * ND];  // [e][n(D)][k(F)]
__device__ __half g_hh[(size_t)NE * NCAP * NF];

// ==================== helpers ====================

__device__ __forceinline__ uint32_t smem_to_u32(const void* smem_ptr) {
    uint32_t addr;
    asm("{ .reg .u64 tmp; cvta.to.shared.u64 tmp, %1; cvt.u32.u64 %0, tmp; }"
        : "=r"(addr) : "l"(smem_ptr));
    return addr;
}

__device__ __forceinline__ void cp16(uint32_t smem_dst, const void* gsrc) {
    size_t gaddr = __cvta_generic_to_global(gsrc);
    asm volatile("cp.async.cg.shared.global [%0], [%1], 16;"
                 :: "r"(smem_dst), "l"(gaddr) : "memory");
}
#define CP_COMMIT() asm volatile("cp.async.commit_group;" ::: "memory")
template<int N>
__device__ __forceinline__ void cp_wait() {
    asm volatile("cp.async.wait_group %0;" :: "n"(N) : "memory");
}

// warp mma: D(16x8,f32) += A(16x16,f16,row) * B(16x8,f16,col)
__device__ __forceinline__ void mma16816h(float* c, const uint32_t* a, const uint32_t* b) {
    asm volatile(
        "mma.sync.aligned.m16n8k16.row.col.f32.f16.f16.f32 "
        "{%0,%1,%2,%3}, {%4,%5,%6,%7}, {%8,%9}, {%0,%1,%2,%3};"
        : "+f"(c[0]), "+f"(c[1]), "+f"(c[2]), "+f"(c[3])
        : "r"(a[0]), "r"(a[1]), "r"(a[2]), "r"(a[3]), "r"(b[0]), "r"(b[1]));
}

__device__ __forceinline__ uint32_t pack_h2(__half a, __half b) {
    unsigned short sa = *reinterpret_cast<unsigned short*>(&a);
    unsigned short sb = *reinterpret_cast<unsigned short*>(&b);
    return (uint32_t)sa | ((uint32_t)sb << 16);
}

__device__ __forceinline__ void cvt8h(const float* f, uint4& hi) {
    unsigned short hs[8];
#pragma unroll
    for (int i = 0; i < 8; i++) {
        __half h = __float2half_rn(f[i]);
        hs[i] = *reinterpret_cast<unsigned short*>(&h);
    }
    hi.x = (uint32_t)hs[0] | ((uint32_t)hs[1] << 16);
    hi.y = (uint32_t)hs[2] | ((uint32_t)hs[3] << 16);
    hi.z = (uint32_t)hs[4] | ((uint32_t)hs[5] << 16);
    hi.w = (uint32_t)hs[6] | ((uint32_t)hs[7] << 16);
}

// ==================== precompute kernels ====================

__global__ void zero_kernel(float* __restrict__ out) {
    int i = blockIdx.x * blockDim.x + threadIdx.x;
    if (i < NT * ND) out[i] = 0.0f;
    if (i < NE) g_count[i] = 0;
}

__global__ void splitx_kernel(const float* __restrict__ x) {
    int i = blockIdx.x * blockDim.x + threadIdx.x;
    if (i < NT * ND / 2) {
        float2 v = ((const float2*)x)[i];
        ((uint32_t*)g_xh)[i] = pack_h2(__float2half_rn(v.x), __float2half_rn(v.y));
    }
}

// transpose W[e][k][n] fp32 -> Wh [e][n][k] fp16
__global__ void splitw_kernel(const float* __restrict__ Wsrc,
                              int kdim, int ndim, int which) {
    __shared__ float tile[64][65];
    int e = blockIdx.z;
    int n0 = blockIdx.x * 64;
    int k0 = blockIdx.y * 64;
    int tid = threadIdx.x;
    const float* src = Wsrc + (size_t)e * (size_t)kdim * (size_t)ndim;
#pragma unroll
    for (int i = 0; i < 16; i++) {
        int r = (tid >> 6) + i * 4;
        int c = tid & 63;
        tile[r][c] = src[(size_t)(k0 + r) * ndim + n0 + c];
    }
    __syncthreads();
    __half* Wh = which ? g_w1h : g_w2h;
    size_t base = (size_t)e * (size_t)kdim * (size_t)ndim;
    int nl = tid >> 2;
    int kq = (tid & 3) * 16;
#pragma unroll
    for (int half = 0; half < 2; half++) {
        float fv[8];
#pragma unroll
        for (int j = 0; j < 8; j++) fv[j] = tile[kq + half * 8 + j][nl];
        uint4 hi;
        cvt8h(fv, hi);
        size_t o = base + (size_t)(n0 + nl) * kdim + k0 + kq + half * 8;
        *(uint4*)(Wh + o) = hi;
    }
}

__global__ void router_kernel(const float* __restrict__ x,
                              const float* __restrict__ Wr,
                              const float* __restrict__ br) {
    int t = blockIdx.x;
    int lane = threadIdx.x;
    float acc[NE];
#pragma unroll
    for (int e = 0; e < NE; e++) acc[e] = 0.0f;
    const float* xr = x + (size_t)t * ND;
    for (int d = lane; d < ND; d += 32) {
        float xv = xr[d];
        const float* wr = Wr + (size_t)d * NE;
#pragma unroll
        for (int e = 0; e < NE; e++) acc[e] += xv * wr[e];
    }
#pragma unroll
    for (int e = 0; e < NE; e++) {
#pragma unroll
        for (int off = 16; off > 0; off >>= 1)
            acc[e] += __shfl_xor_sync(0xffffffffu, acc[e], off);
    }
    if (lane == 0) {
#pragma unroll
        for (int e = 0; e < NE; e++) acc[e] += br[e];
        int i0 = 0;
#pragma unroll
        for (int e = 1; e < NE; e++) if (acc[e] > acc[i0]) i0 = e;
        int i1 = (i0 == 0) ? 1 : 0;
#pragma unroll
        for (int e = 0; e < NE; e++) {
            if (e == i0) continue;
            if (acc[e] > acc[i1] || (acc[e] == acc[i1] && e < i1)) i1 = e;
        }
        float l0 = acc[i0], l1 = acc[i1];
        float e1 = expf(l1 - l0);
        float w0 = 1.0f / (1.0f + e1);
        float w1 = e1 * w0;
        int p0 = atomicAdd(&g_count[i0], 1);
        g_tok[i0 * NCAP + p0] = t;  g_wgt[i0 * NCAP + p0] = w0;
        int p1 = atomicAdd(&g_count[i1], 1);
        g_tok[i1 * NCAP + p1] = t;  g_wgt[i1 * NCAP + p1] = w1;
    }
}

// ==================== fp16 HMMA GEMM, cp.async double-buffered, TBK=64 ====================
#define OFF_BH (TBM * ROWB)                 // 18432
#define STAGEB (2 * TBM * ROWB)             // 36864
#define SMEM_REQ (2 * STAGEB + 512)

__global__ __launch_bounds__(NTHREADS, 2) void moe_mma_gemm(
    const float* __restrict__ bias,
    float* __restrict__ out,
    int kdim, int ldb, int is_ffn1)
{
    int e = blockIdx.z;
    int ne = g_count[e];
    int m0 = blockIdx.y * TBM;
    if (m0 >= ne) return;
    int n0 = blockIdx.x * TBN;
    int tid = threadIdx.x;
    int warp = tid >> 5;
    int lane = tid & 31;
    int wm = warp >> 2;
    int wn = warp & 3;
    int grp = lane >> 2;
    int tig = lane & 3;

    extern __shared__ char smbase[];
    uint32_t smu = smem_to_u32(smbase);
    int* rows = (int*)(smbase + 2 * STAGEB);

    if (is_ffn1 && tid < TBM) {
        int m = m0 + tid;
        rows[tid] = (m < ne) ? g_tok[e * NCAP + m] : -1;
    }
    __syncthreads();

    const __half* Whb = (is_ffn1 ? g_w1h : g_w2h) + (size_t)e * (size_t)kdim * (size_t)ldb;
    const __half* Ahb = is_ffn1 ? g_xh : (g_hh + (size_t)e * NCAP * NF);
    size_t arow_stride = is_ffn1 ? ND : NF;

    auto fill = [&](int s, int kb) {
        int k0 = kb * TBK;
        uint32_t sb = smu + s * STAGEB;
        char* sp = smbase + s * STAGEB;
#pragma unroll
        for (int i = 0; i < 4; i++) {
            int u = tid + i * NTHREADS;   // 0..1023
            int row = u >> 3;
            int part = u & 7;
            uint32_t off = row * ROWB + part * 16;
            long arow;
            if (is_ffn1) arow = rows[row];
            else         arow = (m0 + row < ne) ? (m0 + row) : -1;
            if (arow >= 0) {
                const __half* sh = Ahb + (size_t)arow * arow_stride + k0 + part * 8;
                cp16(sb + off, sh);
            } else {
                *(uint4*)(sp + off) = make_uint4(0, 0, 0, 0);
            }
            const __half* bh = Whb + (size_t)(n0 + row) * kdim + k0 + part * 8;
            cp16(sb + OFF_BH + off, bh);
        }
    };

    float acc[4][4][4];
#pragma unroll
    for (int i = 0; i < 4; i++)
#pragma unroll
        for (int j = 0; j < 4; j++)
#pragma unroll
            for (int q = 0; q < 4; q++) acc[i][j][q] = 0.0f;

    int nb = kdim / TBK;
    fill(0, 0);
    CP_COMMIT();

    for (int kb = 0; kb < nb; kb++) {
        if (kb + 1 < nb) {
            fill((kb + 1) & 1, kb + 1);
            CP_COMMIT();
            cp_wait<1>();
        } else {
            cp_wait<0>();
        }
        __syncthreads();

        char* sp = smbase + (kb & 1) * STAGEB;
#pragma unroll
        for (int s = 0; s < 4; s++) {
            int kc = s * 16 + tig * 2;
            uint32_t bhf[4][2];
#pragma unroll
            for (int nt = 0; nt < 4; nt++) {
                int n = wn * 32 + nt * 8 + grp;
                const char* bp = sp + OFF_BH + n * ROWB + kc * 2;
                bhf[nt][0] = *(const uint32_t*)(bp);
                bhf[nt][1] = *(const uint32_t*)(bp + 16);
            }
#pragma unroll
            for (int mt = 0; mt < 4; mt++) {
                int m = wm * 64 + mt * 16 + grp;
                const char* ap0 = sp + m * ROWB + kc * 2;
                const char* ap1 = sp + (m + 8) * ROWB + kc * 2;
                uint32_t ah[4];
                ah[0] = *(const uint32_t*)(ap0);
                ah[1] = *(const uint32_t*)(ap1);
                ah[2] = *(const uint32_t*)(ap0 + 16);
                ah[3] = *(const uint32_t*)(ap1 + 16);
#pragma unroll
                for (int nt = 0; nt < 4; nt++)
                    mma16816h(acc[mt][nt], ah, bhf[nt]);
            }
        }
        __syncthreads();
    }

    // ---- epilogue ----
#pragma unroll
    for (int mt = 0; mt < 4; mt++) {
#pragma unroll
        for (int half = 0; half < 2; half++) {
            int m = m0 + wm * 64 + mt * 16 + grp + half * 8;
            if (m >= ne) continue;
            if (is_ffn1) {
                const float* bb = bias + (size_t)e * NF;
                __half* hh = g_hh + (size_t)e * NCAP * NF + (size_t)m * NF;
#pragma unroll
                for (int nt = 0; nt < 4; nt++) {
                    int n = n0 + wn * 32 + nt * 8 + tig * 2;
                    float v0 = acc[mt][nt][half * 2 + 0] + bb[n];
                    float v1 = acc[mt][nt][half * 2 + 1] + bb[n + 1];
                    v0 = 0.5f * v0 * (1.0f + erff(v0 * 0.70710678118654752f));
                    v1 = 0.5f * v1 * (1.0f + erff(v1 * 0.70710678118654752f));
                    *(uint32_t*)(hh + n) = pack_h2(__float2half_rn(v0), __float2half_rn(v1));
                }
            } else {
                int tok = g_tok[e * NCAP + m];
                float wgt = g_wgt[e * NCAP + m];
                float* orow = out + (size_t)tok * ND;
                const float* bb = bias + (size_t)e * ND;
#pragma unroll
                for (int nt = 0; nt < 4; nt++) {
                    int n = n0 + wn * 32 + nt * 8 + tig * 2;
                    float v0 = wgt * (acc[mt][nt][half * 2 + 0] + bb[n]);
                    float v1 = wgt * (acc[mt][nt][half * 2 + 1] + bb[n + 1]);
                    atomicAdd(&orow[n], v0);
                    atomicAdd(&orow[n + 1], v1);
                }
            }
        }
    }
}

// ==================== host launcher ====================

extern "C" void kernel_launch(void* const* d_in, const int* in_sizes, int n_in,
                              void* d_out, int out_size) {
    const float* x  = (const float*)d_in[0];
    const float* Wr = (const float*)d_in[1];
    const float* br = (const float*)d_in[2];
    const float* W1 = (const float*)d_in[3];
    const float* b1 = (const float*)d_in[4];
    const float* W2 = (const float*)d_in[5];
    const float* b2 = (const float*)d_in[6];
    float* out = (float*)d_out;

    cudaFuncSetAttribute(moe_mma_gemm,
                         cudaFuncAttributeMaxDynamicSharedMemorySize, SMEM_REQ);

    zero_kernel<<<(NT * ND + 255) / 256, 256>>>(out);
    splitx_kernel<<<(NT * ND / 2 + 255) / 256, 256>>>(x);
    splitw_kernel<<<dim3(NF / 64, ND / 64, NE), 256>>>(W1, ND, NF, 1);
    splitw_kernel<<<dim3(ND / 64, NF / 64, NE), 256>>>(W2, NF, ND, 0);
    router_kernel<<<NT, 32>>>(x, Wr, br);
    moe_mma_gemm<<<dim3(NF / TBN, NCAP / TBM, NE), NTHREADS, SMEM_REQ>>>(
        b1, out, ND, NF, 1);
    moe_mma_gemm<<<dim3(ND / TBN, NCAP / TBM, NE), NTHREADS, SMEM_REQ>>>(
        b2, out, NF, ND, 0);
}

// round 15
// speedup vs baseline: 1.6782x; 1.0246x over previous
#include <cuda_runtime.h>
#include <cuda_fp16.h>
#include <math.h>
#include <stdint.h>

#define ND 1024
#define NF 4096
#define NE 8
#define NT 2048
#define NCAP 2048
#define TBM 128
#define TBN 128
#define TBK 64
#define NTHREADS 256
#define ROWB 144   // smem row stride bytes (128 data + 16 pad)

// -------- scratch (device globals; no allocations allowed) --------
__device__ int   g_count[NE];
__device__ int   g_tok[NE * NCAP];
__device__ float g_wgt[NE * NCAP];
__device__ __half g_xh[(size_t)NT * ND];
__device__ __half g_w1h[(size_t)NE * ND * NF];  // [e][n(F)][k(D)]
__device__ __half g_w2h[(size_t)NE * NF * ND];  // [e][n(D)][k(F)]
__device__ __half g_hh[(size_t)NE * NCAP * NF];

// ==================== helpers ====================

__device__ __forceinline__ uint32_t smem_to_u32(const void* smem_ptr) {
    uint32_t addr;
    asm("{ .reg .u64 tmp; cvta.to.shared.u64 tmp, %1; cvt.u32.u64 %0, tmp; }"
        : "=r"(addr) : "l"(smem_ptr));
    return addr;
}

__device__ __forceinline__ void cp16(uint32_t smem_dst, const void* gsrc) {
    size_t gaddr = __cvta_generic_to_global(gsrc);
    asm volatile("cp.async.cg.shared.global [%0], [%1], 16;"
                 :: "r"(smem_dst), "l"(gaddr) : "memory");
}
#define CP_COMMIT() asm volatile("cp.async.commit_group;" ::: "memory")
template<int N>
__device__ __forceinline__ void cp_wait() {
    asm volatile("cp.async.wait_group %0;" :: "n"(N) : "memory");
}

// warp mma: D(16x8,f32) += A(16x16,f16,row) * B(16x8,f16,col)
__device__ __forceinline__ void mma16816h(float* c, const uint32_t* a, const uint32_t* b) {
    asm volatile(
        "mma.sync.aligned.m16n8k16.row.col.f32.f16.f16.f32 "
        "{%0,%1,%2,%3}, {%4,%5,%6,%7}, {%8,%9}, {%0,%1,%2,%3};"
        : "+f"(c[0]), "+f"(c[1]), "+f"(c[2]), "+f"(c[3])
        : "r"(a[0]), "r"(a[1]), "r"(a[2]), "r"(a[3]), "r"(b[0]), "r"(b[1]));
}

__device__ __forceinline__ uint32_t pack_h2(__half a, __half b) {
    unsigned short sa = *reinterpret_cast<unsigned short*>(&a);
    unsigned short sb = *reinterpret_cast<unsigned short*>(&b);
    return (uint32_t)sa | ((uint32_t)sb << 16);
}

__device__ __forceinline__ void cvt8h(const float* f, uint4& hi) {
    unsigned short hs[8];
#pragma unroll
    for (int i = 0; i < 8; i++) {
        __half h = __float2half_rn(f[i]);
        hs[i] = *reinterpret_cast<unsigned short*>(&h);
    }
    hi.x = (uint32_t)hs[0] | ((uint32_t)hs[1] << 16);
    hi.y = (uint32_t)hs[2] | ((uint32_t)hs[3] << 16);
    hi.z = (uint32_t)hs[4] | ((uint32_t)hs[5] << 16);
    hi.w = (uint32_t)hs[6] | ((uint32_t)hs[7] << 16);
}

// W-tile convert helper: one 64x64 tile, transpose+fp16
// src layout [k][n] (n contiguous, ndim), dst layout [n][k] (k contiguous, kdim)
__device__ __forceinline__ void convert_tile(const float* src, __half* dst,
                                             int kdim, int ndim,
                                             int n0, int k0, int tid,
                                             float (*tile)[65]) {
#pragma unroll
    for (int i = 0; i < 16; i++) {
        int r = (tid >> 6) + i * 4;
        int c = tid & 63;
        tile[r][c] = src[(size_t)(k0 + r) * ndim + n0 + c];
    }
    __syncthreads();
    int nl = tid >> 2;
    int kq = (tid & 3) * 16;
#pragma unroll
    for (int half = 0; half < 2; half++) {
        float fv[8];
#pragma unroll
        for (int j = 0; j < 8; j++) fv[j] = tile[kq + half * 8 + j][nl];
        uint4 hi;
        cvt8h(fv, hi);
        size_t o = (size_t)(n0 + nl) * kdim + k0 + kq + half * 8;
        *(uint4*)(dst + o) = hi;
    }
    __syncthreads();
}

// ==================== precompute kernels ====================

__global__ void zero_kernel(float* __restrict__ out) {
    int i = blockIdx.x * blockDim.x + threadIdx.x;
    if (i < NT * ND) out[i] = 0.0f;
    if (i < NE) g_count[i] = 0;
}

__global__ void splitx_kernel(const float* __restrict__ x) {
    int i = blockIdx.x * blockDim.x + threadIdx.x;
    if (i < NT * ND / 2) {
        float2 v = ((const float2*)x)[i];
        ((uint32_t*)g_xh)[i] = pack_h2(__float2half_rn(v.x), __float2half_rn(v.y));
    }
}

// W1 standalone convert (needed before GEMM1)
__global__ void splitw1_kernel(const float* __restrict__ Wsrc) {
    __shared__ float tile[64][65];
    int e = blockIdx.z;
    int n0 = blockIdx.x * 64;
    int k0 = blockIdx.y * 64;
    convert_tile(Wsrc + (size_t)e * ND * NF, g_w1h + (size_t)e * ND * NF,
                 ND, NF, n0, k0, threadIdx.x, tile);
}

__global__ void router_kernel(const float* __restrict__ x,
                              const float* __restrict__ Wr,
                              const float* __restrict__ br) {
    int t = blockIdx.x;
    int lane = threadIdx.x;
    float acc[NE];
#pragma unroll
    for (int e = 0; e < NE; e++) acc[e] = 0.0f;
    const float* xr = x + (size_t)t * ND;
    for (int d = lane; d < ND; d += 32) {
        float xv = xr[d];
        const float* wr = Wr + (size_t)d * NE;
#pragma unroll
        for (int e = 0; e < NE; e++) acc[e] += xv * wr[e];
    }
#pragma unroll
    for (int e = 0; e < NE; e++) {
#pragma unroll
        for (int off = 16; off > 0; off >>= 1)
            acc[e] += __shfl_xor_sync(0xffffffffu, acc[e], off);
    }
    if (lane == 0) {
#pragma unroll
        for (int e = 0; e < NE; e++) acc[e] += br[e];
        int i0 = 0;
#pragma unroll
        for (int e = 1; e < NE; e++) if (acc[e] > acc[i0]) i0 = e;
        int i1 = (i0 == 0) ? 1 : 0;
#pragma unroll
        for (int e = 0; e < NE; e++) {
            if (e == i0) continue;
            if (acc[e] > acc[i1] || (acc[e] == acc[i1] && e < i1)) i1 = e;
        }
        float l0 = acc[i0], l1 = acc[i1];
        float e1 = expf(l1 - l0);
        float w0 = 1.0f / (1.0f + e1);
        float w1 = e1 * w0;
        int p0 = atomicAdd(&g_count[i0], 1);
        g_tok[i0 * NCAP + p0] = t;  g_wgt[i0 * NCAP + p0] = w0;
        int p1 = atomicAdd(&g_count[i1], 1);
        g_tok[i1 * NCAP + p1] = t;  g_wgt[i1 * NCAP + p1] = w1;
    }
}

// ==================== fp16 HMMA GEMM core (TBK=64, cp.async double-buffered) ====================
#define OFF_BH (TBM * ROWB)
#define STAGEB (2 * TBM * ROWB)
#define SMEM_REQ (2 * STAGEB + 512)

// GEMM1 block count: (NF/TBN)*(NCAP/TBM)*NE = 32*16*8 = 4096
#define NBLK_G1 4096
// W2 convert: 8192 64x64 tiles, 4 per block -> 2048 blocks
#define NBLK_CV 2048

__device__ __forceinline__ void gemm_tile_body(
    const float* bias, float* out,
    int kdim, int ldb, int is_ffn1,
    int e, int m0, int n0,
    char* smbase)
{
    int ne = g_count[e];
    if (m0 >= ne) return;
    int tid = threadIdx.x;
    int warp = tid >> 5;
    int lane = tid & 31;
    int wm = warp >> 2;
    int wn = warp & 3;
    int grp = lane >> 2;
    int tig = lane & 3;

    uint32_t smu = smem_to_u32(smbase);
    int* rows = (int*)(smbase + 2 * STAGEB);

    if (is_ffn1 && tid < TBM) {
        int m = m0 + tid;
        rows[tid] = (m < ne) ? g_tok[e * NCAP + m] : -1;
    }
    __syncthreads();

    const __half* Whb = (is_ffn1 ? g_w1h : g_w2h) + (size_t)e * (size_t)kdim * (size_t)ldb;
    const __half* Ahb = is_ffn1 ? g_xh : (g_hh + (size_t)e * NCAP * NF);
    size_t arow_stride = is_ffn1 ? ND : NF;

    auto fill = [&](int s, int kb) {
        int k0 = kb * TBK;
        uint32_t sb = smu + s * STAGEB;
        char* sp = smbase + s * STAGEB;
#pragma unroll
        for (int i = 0; i < 4; i++) {
            int u = tid + i * NTHREADS;
            int row = u >> 3;
            int part = u & 7;
            uint32_t off = row * ROWB + part * 16;
            long arow;
            if (is_ffn1) arow = rows[row];
            else         arow = (m0 + row < ne) ? (m0 + row) : -1;
            if (arow >= 0) {
                const __half* sh = Ahb + (size_t)arow * arow_stride + k0 + part * 8;
                cp16(sb + off, sh);
            } else {
                *(uint4*)(sp + off) = make_uint4(0, 0, 0, 0);
            }
            const __half* bh = Whb + (size_t)(n0 + row) * kdim + k0 + part * 8;
            cp16(sb + OFF_BH + off, bh);
        }
    };

    float acc[4][4][4];
#pragma unroll
    for (int i = 0; i < 4; i++)
#pragma unroll
        for (int j = 0; j < 4; j++)
#pragma unroll
            for (int q = 0; q < 4; q++) acc[i][j][q] = 0.0f;

    int nb = kdim / TBK;
    fill(0, 0);
    CP_COMMIT();

    for (int kb = 0; kb < nb; kb++) {
        if (kb + 1 < nb) {
            fill((kb + 1) & 1, kb + 1);
            CP_COMMIT();
            cp_wait<1>();
        } else {
            cp_wait<0>();
        }
        __syncthreads();

        char* sp = smbase + (kb & 1) * STAGEB;
#pragma unroll
        for (int s = 0; s < 4; s++) {
            int kc = s * 16 + tig * 2;
            uint32_t bhf[4][2];
#pragma unroll
            for (int nt = 0; nt < 4; nt++) {
                int n = wn * 32 + nt * 8 + grp;
                const char* bp = sp + OFF_BH + n * ROWB + kc * 2;
                bhf[nt][0] = *(const uint32_t*)(bp);
                bhf[nt][1] = *(const uint32_t*)(bp + 16);
            }
#pragma unroll
            for (int mt = 0; mt < 4; mt++) {
                int m = wm * 64 + mt * 16 + grp;
                const char* ap0 = sp + m * ROWB + kc * 2;
                const char* ap1 = sp + (m + 8) * ROWB + kc * 2;
                uint32_t ah[4];
                ah[0] = *(const uint32_t*)(ap0);
                ah[1] = *(const uint32_t*)(ap1);
                ah[2] = *(const uint32_t*)(ap0 + 16);
                ah[3] = *(const uint32_t*)(ap1 + 16);
#pragma unroll
                for (int nt = 0; nt < 4; nt++)
                    mma16816h(acc[mt][nt], ah, bhf[nt]);
            }
        }
        __syncthreads();
    }

    // ---- epilogue ----
#pragma unroll
    for (int mt = 0; mt < 4; mt++) {
#pragma unroll
        for (int half = 0; half < 2; half++) {
            int m = m0 + wm * 64 + mt * 16 + grp + half * 8;
            if (m >= ne) continue;
            if (is_ffn1) {
                const float* bb = bias + (size_t)e * NF;
                __half* hh = g_hh + (size_t)e * NCAP * NF + (size_t)m * NF;
#pragma unroll
                for (int nt = 0; nt < 4; nt++) {
                    int n = n0 + wn * 32 + nt * 8 + tig * 2;
                    float v0 = acc[mt][nt][half * 2 + 0] + bb[n];
                    float v1 = acc[mt][nt][half * 2 + 1] + bb[n + 1];
                    v0 = 0.5f * v0 * (1.0f + erff(v0 * 0.70710678118654752f));
                    v1 = 0.5f * v1 * (1.0f + erff(v1 * 0.70710678118654752f));
                    *(uint32_t*)(hh + n) = pack_h2(__float2half_rn(v0), __float2half_rn(v1));
                }
            } else {
                int tok = g_tok[e * NCAP + m];
                float wgt = g_wgt[e * NCAP + m];
                float* orow = out + (size_t)tok * ND;
                const float* bb = bias + (size_t)e * ND;
#pragma unroll
                for (int nt = 0; nt < 4; nt++) {
                    int n = n0 + wn * 32 + nt * 8 + tig * 2;
                    float v0 = wgt * (acc[mt][nt][half * 2 + 0] + bb[n]);
                    float v1 = wgt * (acc[mt][nt][half * 2 + 1] + bb[n + 1]);
                    atomicAdd(&orow[n], v0);
                    atomicAdd(&orow[n + 1], v1);
                }
            }
        }
    }
}

// ---- GEMM1 fused with W2 conversion (1D grid, 2:1 interleave) ----
__global__ __launch_bounds__(NTHREADS, 2) void gemm1_fused_kernel(
    const float* __restrict__ b1,
    const float* __restrict__ W2src)
{
    extern __shared__ char smbase[];
    int bid = blockIdx.x;
    int g = bid % 3;
    int q = bid / 3;
    if (g < 2) {
        // GEMM1 tile: index 0..4095
        int gi = q * 2 + g;
        int e = gi >> 9;               // 512 tiles per expert (32 n x 16 m)
        int rem = gi & 511;
        int n0 = (rem & 31) * TBN;
        int m0 = (rem >> 5) * TBM;
        gemm_tile_body(b1, nullptr, ND, NF, 1, e, m0, n0, smbase);
    } else {
        // W2 convert: 4 consecutive 64x64 tiles
        float (*tile)[65] = (float(*)[65])smbase;
        int tid = threadIdx.x;
#pragma unroll
        for (int j = 0; j < 4; j++) {
            int t = q * 4 + j;          // 0..8191
            int e = t >> 10;            // 1024 tiles per expert (16 n x 64 k)
            int rem = t & 1023;
            int n0 = (rem & 15) * 64;
            int k0 = (rem >> 4) * 64;
            convert_tile(W2src + (size_t)e * NF * ND, g_w2h + (size_t)e * NF * ND,
                         NF, ND, n0, k0, tid, tile);
        }
    }
}

// ---- GEMM2 standalone ----
__global__ __launch_bounds__(NTHREADS, 2) void gemm2_kernel(
    const float* __restrict__ b2,
    float* __restrict__ out)
{
    extern __shared__ char smbase[];
    int e = blockIdx.z;
    int m0 = blockIdx.y * TBM;
    int n0 = blockIdx.x * TBN;
    gemm_tile_body(b2, out, NF, ND, 0, e, m0, n0, smbase);
}

// ==================== host launcher ====================

extern "C" void kernel_launch(void* const* d_in, const int* in_sizes, int n_in,
                              void* d_out, int out_size) {
    const float* x  = (const float*)d_in[0];
    const float* Wr = (const float*)d_in[1];
    const float* br = (const float*)d_in[2];
    const float* W1 = (const float*)d_in[3];
    const float* b1 = (const float*)d_in[4];
    const float* W2 = (const float*)d_in[5];
    const float* b2 = (const float*)d_in[6];
    float* out = (float*)d_out;

    cudaFuncSetAttribute(gemm1_fused_kernel,
                         cudaFuncAttributeMaxDynamicSharedMemorySize, SMEM_REQ);
    cudaFuncSetAttribute(gemm2_kernel,
                         cudaFuncAttributeMaxDynamicSharedMemorySize, SMEM_REQ);

    zero_kernel<<<(NT * ND + 255) / 256, 256>>>(out);
    splitx_kernel<<<(NT * ND / 2 + 255) / 256, 256>>>(x);
    splitw1_kernel<<<dim3(NF / 64, ND / 64, NE), 256>>>(W1);
    router_kernel<<<NT, 32>>>(x, Wr, br);
    gemm1_fused_kernel<<<NBLK_G1 + NBLK_CV, NTHREADS, SMEM_REQ>>>(b1, W2);
    gemm2_kernel<<<dim3(ND / TBN, NCAP / TBM, NE), NTHREADS, SMEM_REQ>>>(b2, out);
}

// round 16
// speedup vs baseline: 1.7561x; 1.0464x over previous
#include <cuda_runtime.h>
#include <cuda_fp16.h>
#include <math.h>
#include <stdint.h>

#define ND 1024
#define NF 4096
#define NE 8
#define NT 2048
#define NCAP 2048
#define TBM 128
#define TBN 128
#define TBK 64
#define NTHREADS 256
#define ROWB 144   // smem row stride bytes (128 data + 16 pad)

// -------- scratch (device globals; no allocations allowed) --------
__device__ int   g_count[NE];
__device__ int   g_tok[NE * NCAP];
__device__ float g_wgt[NE * NCAP];
__device__ __half g_xh[(size_t)NT * ND];
__device__ __half g_w1h[(size_t)NE * ND * NF];  // [e][n(F)][k(D)]
__device__ __half g_w2h[(size_t)NE * NF * ND];  // [e][n(D)][k(F)]
__device__ __half g_hh[(size_t)NE * NCAP * NF];

// ==================== helpers ====================

__device__ __forceinline__ uint32_t smem_to_u32(const void* smem_ptr) {
    uint32_t addr;
    asm("{ .reg .u64 tmp; cvta.to.shared.u64 tmp, %1; cvt.u32.u64 %0, tmp; }"
        : "=r"(addr) : "l"(smem_ptr));
    return addr;
}

__device__ __forceinline__ void cp16(uint32_t smem_dst, const void* gsrc) {
    size_t gaddr = __cvta_generic_to_global(gsrc);
    asm volatile("cp.async.cg.shared.global [%0], [%1], 16;"
                 :: "r"(smem_dst), "l"(gaddr) : "memory");
}
#define CP_COMMIT() asm volatile("cp.async.commit_group;" ::: "memory")
template<int N>
__device__ __forceinline__ void cp_wait() {
    asm volatile("cp.async.wait_group %0;" :: "n"(N) : "memory");
}

// warp mma: D(16x8,f32) += A(16x16,f16,row) * B(16x8,f16,col)
__device__ __forceinline__ void mma16816h(float* c, const uint32_t* a, const uint32_t* b) {
    asm volatile(
        "mma.sync.aligned.m16n8k16.row.col.f32.f16.f16.f32 "
        "{%0,%1,%2,%3}, {%4,%5,%6,%7}, {%8,%9}, {%0,%1,%2,%3};"
        : "+f"(c[0]), "+f"(c[1]), "+f"(c[2]), "+f"(c[3])
        : "r"(a[0]), "r"(a[1]), "r"(a[2]), "r"(a[3]), "r"(b[0]), "r"(b[1]));
}

__device__ __forceinline__ uint32_t pack_h2(__half a, __half b) {
    unsigned short sa = *reinterpret_cast<unsigned short*>(&a);
    unsigned short sb = *reinterpret_cast<unsigned short*>(&b);
    return (uint32_t)sa | ((uint32_t)sb << 16);
}

__device__ __forceinline__ void cvt8h(const float* f, uint4& hi) {
    unsigned short hs[8];
#pragma unroll
    for (int i = 0; i < 8; i++) {
        __half h = __float2half_rn(f[i]);
        hs[i] = *reinterpret_cast<unsigned short*>(&h);
    }
    hi.x = (uint32_t)hs[0] | ((uint32_t)hs[1] << 16);
    hi.y = (uint32_t)hs[2] | ((uint32_t)hs[3] << 16);
    hi.z = (uint32_t)hs[4] | ((uint32_t)hs[5] << 16);
    hi.w = (uint32_t)hs[6] | ((uint32_t)hs[7] << 16);
}

// W-tile convert helper: one 64x64 tile, transpose+fp16
__device__ __forceinline__ void convert_tile(const float* src, __half* dst,
                                             int kdim, int ndim,
                                             int n0, int k0, int tid,
                                             float (*tile)[65]) {
#pragma unroll
    for (int i = 0; i < 16; i++) {
        int r = (tid >> 6) + i * 4;
        int c = tid & 63;
        tile[r][c] = src[(size_t)(k0 + r) * ndim + n0 + c];
    }
    __syncthreads();
    int nl = tid >> 2;
    int kq = (tid & 3) * 16;
#pragma unroll
    for (int half = 0; half < 2; half++) {
        float fv[8];
#pragma unroll
        for (int j = 0; j < 8; j++) fv[j] = tile[kq + half * 8 + j][nl];
        uint4 hi;
        cvt8h(fv, hi);
        size_t o = (size_t)(n0 + nl) * kdim + k0 + kq + half * 8;
        *(uint4*)(dst + o) = hi;
    }
    __syncthreads();
}

// ==================== precompute kernels ====================

__global__ void zero_kernel(float* __restrict__ out) {
    int i = blockIdx.x * blockDim.x + threadIdx.x;
    if (i < NT * ND) out[i] = 0.0f;
    if (i < NE) g_count[i] = 0;
}

// W1 standalone convert (needed before GEMM1)
__global__ void splitw1_kernel(const float* __restrict__ Wsrc) {
    __shared__ float tile[64][65];
    int e = blockIdx.z;
    int n0 = blockIdx.x * 64;
    int k0 = blockIdx.y * 64;
    convert_tile(Wsrc + (size_t)e * ND * NF, g_w1h + (size_t)e * ND * NF,
                 ND, NF, n0, k0, threadIdx.x, tile);
}

// fused: router (top-2 dispatch) + x fp16 conversion. 8 warps = 8 tokens/CTA.
__global__ __launch_bounds__(256) void router_splitx_kernel(
    const float* __restrict__ x,
    const float* __restrict__ Wr,
    const float* __restrict__ br)
{
    __shared__ float wrs[ND * NE / 128];   // staged in chunks? no: full 32KB
    // full Wr: ND*NE = 8192 floats = 32KB
    __shared__ float wr_full[ND * NE];
    int tid = threadIdx.x;
#pragma unroll
    for (int i = 0; i < ND * NE / 256; i++)
        wr_full[tid + i * 256] = Wr[tid + i * 256];
    (void)wrs;
    __syncthreads();

    int warp = tid >> 5;
    int lane = tid & 31;
    int t = blockIdx.x * 8 + warp;

    const float2* xr = (const float2*)(x + (size_t)t * ND);
    uint32_t* xh = (uint32_t*)(g_xh + (size_t)t * ND);

    float acc[NE];
#pragma unroll
    for (int e = 0; e < NE; e++) acc[e] = 0.0f;

#pragma unroll
    for (int i = 0; i < ND / 64; i++) {       // 16 iters
        int d2 = lane + i * 32;                // float2 index
        float2 v = xr[d2];
        xh[d2] = pack_h2(__float2half_rn(v.x), __float2half_rn(v.y));
        const float* w0 = wr_full + (2 * d2) * NE;
#pragma unroll
        for (int e = 0; e < NE; e++) acc[e] += v.x * w0[e] + v.y * w0[NE + e];
    }
#pragma unroll
    for (int e = 0; e < NE; e++) {
#pragma unroll
        for (int off = 16; off > 0; off >>= 1)
            acc[e] += __shfl_xor_sync(0xffffffffu, acc[e], off);
    }
    if (lane == 0) {
#pragma unroll
        for (int e = 0; e < NE; e++) acc[e] += br[e];
        int i0 = 0;
#pragma unroll
        for (int e = 1; e < NE; e++) if (acc[e] > acc[i0]) i0 = e;
        int i1 = (i0 == 0) ? 1 : 0;
#pragma unroll
        for (int e = 0; e < NE; e++) {
            if (e == i0) continue;
            if (acc[e] > acc[i1] || (acc[e] == acc[i1] && e < i1)) i1 = e;
        }
        float l0 = acc[i0], l1 = acc[i1];
        float e1 = expf(l1 - l0);
        float w0 = 1.0f / (1.0f + e1);
        float w1 = e1 * w0;
        int p0 = atomicAdd(&g_count[i0], 1);
        g_tok[i0 * NCAP + p0] = t;  g_wgt[i0 * NCAP + p0] = w0;
        int p1 = atomicAdd(&g_count[i1], 1);
        g_tok[i1 * NCAP + p1] = t;  g_wgt[i1 * NCAP + p1] = w1;
    }
}

// ==================== fp16 HMMA GEMM core (TBK=64, cp.async double-buffered) ====================
#define OFF_BH (TBM * ROWB)
#define STAGEB (2 * TBM * ROWB)
#define SMEM_REQ (2 * STAGEB + 512)

#define NBLK_G1 4096
#define NBLK_CV 2048

__device__ __forceinline__ void gemm_tile_body(
    const float* bias, float* out,
    int kdim, int ldb, int is_ffn1,
    int e, int m0, int n0,
    char* smbase)
{
    int ne = g_count[e];
    if (m0 >= ne) return;
    int tid = threadIdx.x;
    int warp = tid >> 5;
    int lane = tid & 31;
    int wm = warp >> 2;
    int wn = warp & 3;
    int grp = lane >> 2;
    int tig = lane & 3;

    uint32_t smu = smem_to_u32(smbase);
    int* rows = (int*)(smbase + 2 * STAGEB);

    if (is_ffn1 && tid < TBM) {
        int m = m0 + tid;
        rows[tid] = (m < ne) ? g_tok[e * NCAP + m] : -1;
    }
    __syncthreads();

    const __half* Whb = (is_ffn1 ? g_w1h : g_w2h) + (size_t)e * (size_t)kdim * (size_t)ldb;
    const __half* Ahb = is_ffn1 ? g_xh : (g_hh + (size_t)e * NCAP * NF);
    size_t arow_stride = is_ffn1 ? ND : NF;

    auto fill = [&](int s, int kb) {
        int k0 = kb * TBK;
        uint32_t sb = smu + s * STAGEB;
        char* sp = smbase + s * STAGEB;
#pragma unroll
        for (int i = 0; i < 4; i++) {
            int u = tid + i * NTHREADS;
            int row = u >> 3;
            int part = u & 7;
            uint32_t off = row * ROWB + part * 16;
            long arow;
            if (is_ffn1) arow = rows[row];
            else         arow = (m0 + row < ne) ? (m0 + row) : -1;
            if (arow >= 0) {
                const __half* sh = Ahb + (size_t)arow * arow_stride + k0 + part * 8;
                cp16(sb + off, sh);
            } else {
                *(uint4*)(sp + off) = make_uint4(0, 0, 0, 0);
            }
            const __half* bh = Whb + (size_t)(n0 + row) * kdim + k0 + part * 8;
            cp16(sb + OFF_BH + off, bh);
        }
    };

    float acc[4][4][4];
#pragma unroll
    for (int i = 0; i < 4; i++)
#pragma unroll
        for (int j = 0; j < 4; j++)
#pragma unroll
            for (int q = 0; q < 4; q++) acc[i][j][q] = 0.0f;

    int nb = kdim / TBK;
    fill(0, 0);
    CP_COMMIT();

    for (int kb = 0; kb < nb; kb++) {
        if (kb + 1 < nb) {
            fill((kb + 1) & 1, kb + 1);
            CP_COMMIT();
            cp_wait<1>();
        } else {
            cp_wait<0>();
        }
        __syncthreads();

        char* sp = smbase + (kb & 1) * STAGEB;
#pragma unroll
        for (int s = 0; s < 4; s++) {
            int kc = s * 16 + tig * 2;
            uint32_t bhf[4][2];
#pragma unroll
            for (int nt = 0; nt < 4; nt++) {
                int n = wn * 32 + nt * 8 + grp;
                const char* bp = sp + OFF_BH + n * ROWB + kc * 2;
                bhf[nt][0] = *(const uint32_t*)(bp);
                bhf[nt][1] = *(const uint32_t*)(bp + 16);
            }
#pragma unroll
            for (int mt = 0; mt < 4; mt++) {
                int m = wm * 64 + mt * 16 + grp;
                const char* ap0 = sp + m * ROWB + kc * 2;
                const char* ap1 = sp + (m + 8) * ROWB + kc * 2;
                uint32_t ah[4];
                ah[0] = *(const uint32_t*)(ap0);
                ah[1] = *(const uint32_t*)(ap1);
                ah[2] = *(const uint32_t*)(ap0 + 16);
                ah[3] = *(const uint32_t*)(ap1 + 16);
#pragma unroll
                for (int nt = 0; nt < 4; nt++)
                    mma16816h(acc[mt][nt], ah, bhf[nt]);
            }
        }
        __syncthreads();
    }

    // ---- epilogue ----
#pragma unroll
    for (int mt = 0; mt < 4; mt++) {
#pragma unroll
        for (int half = 0; half < 2; half++) {
            int m = m0 + wm * 64 + mt * 16 + grp + half * 8;
            if (m >= ne) continue;
            if (is_ffn1) {
                const float* bb = bias + (size_t)e * NF;
                __half* hh = g_hh + (size_t)e * NCAP * NF + (size_t)m * NF;
#pragma unroll
                for (int nt = 0; nt < 4; nt++) {
                    int n = n0 + wn * 32 + nt * 8 + tig * 2;
                    float v0 = acc[mt][nt][half * 2 + 0] + bb[n];
                    float v1 = acc[mt][nt][half * 2 + 1] + bb[n + 1];
                    v0 = 0.5f * v0 * (1.0f + erff(v0 * 0.70710678118654752f));
                    v1 = 0.5f * v1 * (1.0f + erff(v1 * 0.70710678118654752f));
                    *(uint32_t*)(hh + n) = pack_h2(__float2half_rn(v0), __float2half_rn(v1));
                }
            } else {
                int tok = g_tok[e * NCAP + m];
                float wgt = g_wgt[e * NCAP + m];
                float* orow = out + (size_t)tok * ND;
                const float* bb = bias + (size_t)e * ND;
#pragma unroll
                for (int nt = 0; nt < 4; nt++) {
                    int n = n0 + wn * 32 + nt * 8 + tig * 2;
                    float v0 = wgt * (acc[mt][nt][half * 2 + 0] + bb[n]);
                    float v1 = wgt * (acc[mt][nt][half * 2 + 1] + bb[n + 1]);
                    atomicAdd(&orow[n], v0);
                    atomicAdd(&orow[n + 1], v1);
                }
            }
        }
    }
}

// ---- GEMM1 fused with W2 conversion (1D grid, 2:1 interleave) ----
__global__ __launch_bounds__(NTHREADS, 2) void gemm1_fused_kernel(
    const float* __restrict__ b1,
    const float* __restrict__ W2src)
{
    extern __shared__ char smbase[];
    int bid = blockIdx.x;
    int g = bid % 3;
    int q = bid / 3;
    if (g < 2) {
        int gi = q * 2 + g;
        int e = gi >> 9;
        int rem = gi & 511;
        int n0 = (rem & 31) * TBN;
        int m0 = (rem >> 5) * TBM;
        gemm_tile_body(b1, nullptr, ND, NF, 1, e, m0, n0, smbase);
    } else {
        float (*tile)[65] = (float(*)[65])smbase;
        int tid = threadIdx.x;
#pragma unroll
        for (int j = 0; j < 4; j++) {
            int t = q * 4 + j;
            int e = t >> 10;
            int rem = t & 1023;
            int n0 = (rem & 15) * 64;
            int k0 = (rem >> 4) * 64;
            convert_tile(W2src + (size_t)e * NF * ND, g_w2h + (size_t)e * NF * ND,
                         NF, ND, n0, k0, tid, tile);
        }
    }
}

// ---- GEMM2 standalone ----
__global__ __launch_bounds__(NTHREADS, 2) void gemm2_kernel(
    const float* __restrict__ b2,
    float* __restrict__ out)
{
    extern __shared__ char smbase[];
    int e = blockIdx.z;
    int m0 = blockIdx.y * TBM;
    int n0 = blockIdx.x * TBN;
    gemm_tile_body(b2, out, NF, ND, 0, e, m0, n0, smbase);
}

// ==================== host launcher ====================

extern "C" void kernel_launch(void* const* d_in, const int* in_sizes, int n_in,
                              void* d_out, int out_size) {
    const float* x  = (const float*)d_in[0];
    const float* Wr = (const float*)d_in[1];
    const float* br = (const float*)d_in[2];
    const float* W1 = (const float*)d_in[3];
    const float* b1 = (const float*)d_in[4];
    const float* W2 = (const float*)d_in[5];
    const float* b2 = (const float*)d_in[6];
    float* out = (float*)d_out;

    cudaFuncSetAttribute(gemm1_fused_kernel,
                         cudaFuncAttributeMaxDynamicSharedMemorySize, SMEM_REQ);
    cudaFuncSetAttribute(gemm2_kernel,
                         cudaFuncAttributeMaxDynamicSharedMemorySize, SMEM_REQ);

    zero_kernel<<<(NT * ND + 255) / 256, 256>>>(out);
    splitw1_kernel<<<dim3(NF / 64, ND / 64, NE), 256>>>(W1);
    router_splitx_kernel<<<NT / 8, 256>>>(x, Wr, br);
    gemm1_fused_kernel<<<NBLK_G1 + NBLK_CV, NTHREADS, SMEM_REQ>>>(b1, W2);
    gemm2_kernel<<<dim3(ND / TBN, NCAP / TBM, NE), NTHREADS, SMEM_REQ>>>(b2, out);
}